// round 4
// baseline (speedup 1.0000x reference)
#include <cuda_runtime.h>

// ---------------------------------------------------------------------------
// MultitaskSNN round 4: 2 threads per batch element, f32x2 output-pair math.
// Lane pair (2k, 2k+1) shares batch b: even lane owns shared-hidden outputs
// 0..13 + class branch, odd lane owns outputs 14..27 + regression branch.
// Branch/out layers are zero-padded so both lanes run identical code (no
// divergence). Spikes exchanged with SHFL.BFLY. Per-lane arithmetic order is
// identical to the reference (ascending-i FMA chain, bias at end,
// fma(0.9,m,cur)-reset) => bit-exact.
// ---------------------------------------------------------------------------

typedef unsigned long long u64;

#define TT 50
#define NIN 32
#define NSH 28
#define THREADS 448

// smem float offsets
#define O_L1W   0      // [half][row7][i32][2]  halves: 448 + pad4 + 448
#define O_L1B   904    // [half] 14 + pad2 + 14
#define O_BRW   936    // [half][row7][i28][2]  392 + pad4 + 392
#define O_BRB   1724   // 14 + pad2 + 14
#define O_OUTW  1756   // [half][i14][row2][2]  56 + pad4 + 56
#define O_OUTB  1872   // 4 + pad4 + 4
#define SW_TOTAL 1888

#define L1_SKEW 452
#define BR_SKEW 396
#define OW_SKEW 60

__device__ __forceinline__ u64 pack2(float lo, float hi) {
    u64 r; asm("mov.b64 %0, {%1, %2};" : "=l"(r) : "f"(lo), "f"(hi)); return r;
}
__device__ __forceinline__ void unpack2(u64 v, float& lo, float& hi) {
    asm("mov.b64 {%0, %1}, %2;" : "=f"(lo), "=f"(hi) : "l"(v));
}
__device__ __forceinline__ u64 fma2(u64 a, u64 b, u64 c) {
    u64 d; asm("fma.rn.f32x2 %0, %1, %2, %3;" : "=l"(d) : "l"(a), "l"(b), "l"(c)); return d;
}
__device__ __forceinline__ u64 add2(u64 a, u64 b) {
    u64 d; asm("add.rn.f32x2 %0, %1, %2;" : "=l"(d) : "l"(a), "l"(b)); return d;
}

#define BETA2 0x3F6666663F666666ull  // {0.9f, 0.9f}

// packed LIF, per-lane bits identical to: r=(m>1); m=fma(0.9,m,cur)-r; s=(m>1)
__device__ __forceinline__ u64 lif2(u64& m2, u64 cur2) {
    float m0, m1;
    unpack2(m2, m0, m1);
    float r0 = (m0 > 1.0f) ? -1.0f : 0.0f;
    float r1 = (m1 > 1.0f) ? -1.0f : 0.0f;
    m2 = add2(fma2(BETA2, m2, cur2), pack2(r0, r1));
    float n0, n1;
    unpack2(m2, n0, n1);
    return pack2((n0 > 1.0f) ? 1.0f : 0.0f, (n1 > 1.0f) ? 1.0f : 0.0f);
}

__global__ __launch_bounds__(THREADS, 1) void snn_kernel(
    const float* __restrict__ x,
    const float* __restrict__ Wsh, const float* __restrict__ bsh,
    const float* __restrict__ Wch, const float* __restrict__ bch,
    const float* __restrict__ Wco, const float* __restrict__ bco,
    const float* __restrict__ Wrh, const float* __restrict__ brh,
    const float* __restrict__ Wro, const float* __restrict__ bro,
    float* __restrict__ out, int B)
{
    __shared__ __align__(16) float sw[SW_TOTAL];
    const int tid = threadIdx.x;

    // ---- stage interleaved pair-weights ----
    for (int i = tid; i < SW_TOTAL; i += THREADS) sw[i] = 0.0f;
    __syncthreads();
    // L1W: dst[half*452 + r*64 + i*2 + c] = Wsh[(half*14 + 2r + c)*32 + i]
    for (int idx = tid; idx < 896; idx += THREADS) {
        int half = idx / 448, rem = idx % 448;
        int r = rem / 64, t2 = rem % 64, i = t2 >> 1, c = t2 & 1;
        sw[O_L1W + half * L1_SKEW + r * 64 + i * 2 + c] =
            Wsh[(half * 14 + 2 * r + c) * NIN + i];
    }
    // L1B
    for (int idx = tid; idx < 28; idx += THREADS)
        sw[O_L1B + (idx / 14) * 16 + (idx % 14)] = bsh[idx];
    // BRW class (even half): 8 outs -> pair rows 0..3
    for (int idx = tid; idx < 224; idx += THREADS) {
        int o = idx / 28, i = idx % 28;
        sw[O_BRW + (o >> 1) * 56 + i * 2 + (o & 1)] = Wch[idx];
    }
    // BRW reg (odd half): 14 outs -> pair rows 0..6
    for (int idx = tid; idx < 392; idx += THREADS) {
        int o = idx / 28, i = idx % 28;
        sw[O_BRW + BR_SKEW + (o >> 1) * 56 + i * 2 + (o & 1)] = Wrh[idx];
    }
    // BRB
    for (int idx = tid; idx < 8;  idx += THREADS) sw[O_BRB + idx] = bch[idx];
    for (int idx = tid; idx < 14; idx += THREADS) sw[O_BRB + 16 + idx] = brh[idx];
    // OUTW even half [i][k]: k=0->co0, 1->co1, 2->co2, 3->pad
    for (int idx = tid; idx < 24; idx += THREADS) {
        int o = idx / 8, i = idx % 8;
        sw[O_OUTW + i * 4 + o] = Wco[idx];
    }
    // OUTW odd half [i][0] = ro0
    for (int idx = tid; idx < 14; idx += THREADS)
        sw[O_OUTW + OW_SKEW + idx * 4] = Wro[idx];
    if (tid == 0) {
        sw[O_OUTB + 0] = bco[0]; sw[O_OUTB + 1] = bco[1]; sw[O_OUTB + 2] = bco[2];
        sw[O_OUTB + 8] = bro[0];
    }
    __syncthreads();

    const int g = blockIdx.x * THREADS + tid;
    const int b = g >> 1;
    const int h = g & 1;              // 0 = class half, 1 = reg half
    if (b >= B) return;

    const float* l1w = sw + O_L1W + h * L1_SKEW;
    const float* brw = sw + O_BRW + h * BR_SKEW;
    const float* oww = sw + O_OUTW + h * OW_SKEW;
    const u64*   l1b = (const u64*)(sw + O_L1B + h * 16);
    const u64*   brb = (const u64*)(sw + O_BRB + h * 16);
    const u64*   owb = (const u64*)(sw + O_OUTB + h * 8);

    u64 m_sh[7], m_bh[7], m_o0 = 0ull, m_o1 = 0ull;
#pragma unroll
    for (int r = 0; r < 7; r++) { m_sh[r] = 0ull; m_bh[r] = 0ull; }

    const size_t TB = (size_t)TT * B;
    float* p_mco = out;                 // [T,B,3]
    float* p_sch = out + TB * 3;        // [T,B,8]
    float* p_mro = out + TB * 11;       // [T,B,1]
    float* p_srh = out + TB * 12;       // [T,B,14]
    float* p_ssh = out + TB * 26;       // [T,B,28]

#pragma unroll 1
    for (int t = 0; t < TT; t++) {
        const float* xp = x + ((size_t)t * B + b) * NIN;
        if (t + 1 < TT)
            asm volatile("prefetch.global.L2 [%0];" :: "l"(xp + (size_t)B * NIN));

        // ---- Layer 1: 7 output-pairs <- 32 inputs ----
        u64 acc[7];
#pragma unroll
        for (int r = 0; r < 7; r++) acc[r] = 0ull;
#pragma unroll
        for (int c = 0; c < 8; c++) {               // chunks of 4 inputs
            float4 xv = __ldcs((const float4*)xp + c);
            u64 d0 = pack2(xv.x, xv.x), d1 = pack2(xv.y, xv.y);
            u64 d2 = pack2(xv.z, xv.z), d3 = pack2(xv.w, xv.w);
#pragma unroll
            for (int r = 0; r < 7; r++) {
                const u64* w = (const u64*)(l1w + r * 64 + c * 8);
                ulonglong2 w01 = *(const ulonglong2*)w;
                ulonglong2 w23 = *(const ulonglong2*)(w + 2);
                acc[r] = fma2(d0, w01.x, acc[r]);
                acc[r] = fma2(d1, w01.y, acc[r]);
                acc[r] = fma2(d2, w23.x, acc[r]);
                acc[r] = fma2(d3, w23.y, acc[r]);
            }
        }
        u64 own[7];
#pragma unroll
        for (int r = 0; r < 7; r++)
            own[r] = lif2(m_sh[r], add2(acc[r], l1b[r]));

        // store spk_sh: 14 consecutive floats per lane
        {
            float* p = p_ssh + ((size_t)t * B + b) * NSH + h * 14;
#pragma unroll
            for (int r = 0; r < 7; r++) {
                float s0, s1; unpack2(own[r], s0, s1);
                __stcs((float2*)p + r, make_float2(s0, s1));
            }
        }

        // ---- exchange spikes with partner lane ----
        u64 sps[14];
#pragma unroll
        for (int r = 0; r < 7; r++) {
            u64 part = __shfl_xor_sync(0xffffffffu, own[r], 1);
            sps[r]     = h ? part   : own[r];
            sps[7 + r] = h ? own[r] : part;
        }

        // ---- Branch layer: 7 output-pairs <- 28 spikes (padded uniform) ----
#pragma unroll
        for (int r = 0; r < 7; r++) acc[r] = 0ull;
#pragma unroll
        for (int q = 0; q < 14; q += 2) {           // 4 inputs per chunk
            float a0, a1, a2, a3;
            unpack2(sps[q], a0, a1);
            unpack2(sps[q + 1], a2, a3);
            u64 d0 = pack2(a0, a0), d1 = pack2(a1, a1);
            u64 d2 = pack2(a2, a2), d3 = pack2(a3, a3);
#pragma unroll
            for (int r = 0; r < 7; r++) {
                const u64* w = (const u64*)(brw + r * 56 + q * 4);
                ulonglong2 w01 = *(const ulonglong2*)w;
                ulonglong2 w23 = *(const ulonglong2*)(w + 2);
                acc[r] = fma2(d0, w01.x, acc[r]);
                acc[r] = fma2(d1, w01.y, acc[r]);
                acc[r] = fma2(d2, w23.x, acc[r]);
                acc[r] = fma2(d3, w23.y, acc[r]);
            }
        }
        u64 bh[7];
#pragma unroll
        for (int r = 0; r < 7; r++)
            bh[r] = lif2(m_bh[r], add2(acc[r], brb[r]));

        // ---- Out layer: 2 output-pairs <- 14 spikes (padded uniform) ----
        u64 o0 = 0ull, o1 = 0ull;
#pragma unroll
        for (int q = 0; q < 7; q++) {
            float a0, a1; unpack2(bh[q], a0, a1);
            u64 d0 = pack2(a0, a0), d1 = pack2(a1, a1);
            ulonglong2 w0 = *(const ulonglong2*)(oww + (2 * q) * 4);
            ulonglong2 w1 = *(const ulonglong2*)(oww + (2 * q + 1) * 4);
            o0 = fma2(d0, w0.x, o0); o1 = fma2(d0, w0.y, o1);
            o0 = fma2(d1, w1.x, o0); o1 = fma2(d1, w1.y, o1);
        }
        (void)lif2(m_o0, add2(o0, owb[0]));
        (void)lif2(m_o1, add2(o1, owb[1]));

        // ---- per-half stores ----
        if (h == 0) {
            float* p = p_sch + ((size_t)t * B + b) * 8;
#pragma unroll
            for (int r = 0; r < 4; r++) {
                float s0, s1; unpack2(bh[r], s0, s1);
                __stcs((float2*)p + r, make_float2(s0, s1));
            }
            float* q = p_mco + ((size_t)t * B + b) * 3;
            float c0, c1, c2, cd;
            unpack2(m_o0, c0, c1);
            unpack2(m_o1, c2, cd);
            __stcs(q, c0); __stcs(q + 1, c1); __stcs(q + 2, c2);
        } else {
            float* p = p_srh + ((size_t)t * B + b) * 14;
#pragma unroll
            for (int r = 0; r < 7; r++) {
                float s0, s1; unpack2(bh[r], s0, s1);
                __stcs((float2*)p + r, make_float2(s0, s1));
            }
            float r0, rd; unpack2(m_o0, r0, rd);
            __stcs(p_mro + (size_t)t * B + b, r0);
        }
    }
}

extern "C" void kernel_launch(void* const* d_in, const int* in_sizes, int n_in,
                              void* d_out, int out_size) {
    const float* x   = (const float*)d_in[0];
    const float* Wsh = (const float*)d_in[1];
    const float* bsh = (const float*)d_in[2];
    const float* Wch = (const float*)d_in[3];
    const float* bch = (const float*)d_in[4];
    const float* Wco = (const float*)d_in[5];
    const float* bco = (const float*)d_in[6];
    const float* Wrh = (const float*)d_in[7];
    const float* brh = (const float*)d_in[8];
    const float* Wro = (const float*)d_in[9];
    const float* bro = (const float*)d_in[10];

    const int B = in_sizes[0] / (TT * NIN);
    const int total = 2 * B;
    const int blocks = (total + THREADS - 1) / THREADS;

    snn_kernel<<<blocks, THREADS>>>(x, Wsh, bsh, Wch, bch, Wco, bco,
                                    Wrh, brh, Wro, bro, (float*)d_out, B);
}